// round 13
// baseline (speedup 1.0000x reference)
#include <cuda_runtime.h>
#include <cuda_fp16.h>
#include <cstdint>

#define TOK   2048
#define CDIM  2048
#define NHEAD 32
#define DDIM  64
#define KR    1024

#define CTOK  256            // tokens per x tile
#define NTPM  128            // 8-col n-tiles per matrix
#define GSZ   8              // n-tiles per pipeline group
#define CHNT  48             // n-tiles per work unit (6 groups)
#define NUNIT 2048           // 8 tiles x 32 heads x 8 chunks
#define NCTA  296            // exactly 2 CTAs per SM on 148 SMs
#define NT_B  2048           // bytes per n-tile (hi/lo interleaved 16B)
#define GRP_B (GSZ * NT_B)   // 16 KB

#define SM_XPIT 68
#define SM_B    (CTOK * SM_XPIT * 4)          // 69632
#define SM_TOTAL (SM_B + 2 * GRP_B)           // 102400 -> 2 CTAs/SM

__device__ int g_row[NHEAD * TOK];
__device__ unsigned long long g_best[(size_t)3 * NHEAD * TOK];
// W fp16 hi/lo interleaved, fragment-major: [mat][head][ntl][ks][lane]{h0,h1,l0,l1}
__device__ __align__(16) uint8_t g_whf[(size_t)3 * NHEAD * NTPM * NT_B];   // 24 MB

// ---------------- helpers ----------------
static __device__ __forceinline__ uint32_t s2u(const void* p) {
    uint32_t a;
    asm("{ .reg .u64 t; cvta.to.shared.u64 t, %1; cvt.u32.u64 %0, t; }"
        : "=r"(a) : "l"(p));
    return a;
}
static __device__ __forceinline__ uint32_t h2u(__half2 h) {
    uint32_t u; asm("mov.b32 %0, %1;" : "=r"(u) : "r"(*(uint32_t*)&h)); return u;
}
static __device__ __forceinline__ void mma_f16(float* d, const uint32_t* a,
                                               uint32_t b0, uint32_t b1) {
    asm volatile("mma.sync.aligned.m16n8k16.row.col.f32.f16.f16.f32 "
                 "{%0,%1,%2,%3}, {%4,%5,%6,%7}, {%8,%9}, {%0,%1,%2,%3};"
                 : "+f"(d[0]), "+f"(d[1]), "+f"(d[2]), "+f"(d[3])
                 : "r"(a[0]), "r"(a[1]), "r"(a[2]), "r"(a[3]),
                   "r"(b0), "r"(b1));
}
static __device__ __forceinline__ void cp16(uint32_t d, const void* s) {
    asm volatile("cp.async.cg.shared.global [%0], [%1], 16;"
                 :: "r"(d), "l"(s) : "memory");
}
#define CP_COMMIT() asm volatile("cp.async.commit_group;" ::: "memory")
#define CP_WAIT1()  asm volatile("cp.async.wait_group 1;" ::: "memory")
#define CP_WAIT0()  asm volatile("cp.async.wait_group 0;" ::: "memory")

// split one float pair into packed fp16 hi / lo
static __device__ __forceinline__ void split2(float2 v, uint32_t& h, uint32_t& l) {
    __half2 hh = __float22half2_rn(v);
    float2 hf = __half22float2(hh);
    __half2 ll = __float22half2_rn(make_float2(v.x - hf.x, v.y - hf.y));
    h = h2u(hh); l = h2u(ll);
}
// orderable packing: larger logit wins; tie -> smaller col wins; 0 < any real
static __device__ __forceinline__ unsigned long long packcmp(float v, int col) {
    uint32_t b = __float_as_uint(v);
    uint32_t u = (b & 0x80000000u) ? ~b : (b | 0x80000000u);
    return ((unsigned long long)u << 32)
         | (unsigned long long)(0xFFFFFFFFu - (uint32_t)col);
}
static __device__ __forceinline__ int unpack_col(unsigned long long p) {
    return (int)(0xFFFFFFFFu - (uint32_t)(p & 0xFFFFFFFFull));
}

// ---------------------------------------------------------------------------
// Prepass: split W into fp16 hi/lo, fragment-major, hi/lo interleaved 16B.
// id bits: lane[0:5) ks[5:7) ntl[7:14) head[14:19) mat[19:21)
// Also zeroes g_best (first 196608 threads).
// ---------------------------------------------------------------------------
__global__ __launch_bounds__(256) void split_w_kernel(
    const float* __restrict__ wq, const float* __restrict__ wk,
    const float* __restrict__ wv)
{
    uint32_t id = blockIdx.x * 256u + threadIdx.x;
    if (id < 3u * NHEAD * TOK) g_best[id] = 0ull;
    uint32_t lane = id & 31u;
    uint32_t ks   = (id >> 5) & 3u;
    uint32_t ntl  = (id >> 7) & 127u;
    uint32_t head = (id >> 14) & 31u;
    uint32_t mat  = id >> 19;
    const float* W = (mat == 0) ? wq : (mat == 1) ? wk : wv;
    int col = (int)(ntl * 8 + (lane >> 2));
    int k0  = (int)(ks * 16 + 2 * (lane & 3));
    size_t off = ((size_t)head * KR + col) * DDIM + k0;
    float2 v0 = *reinterpret_cast<const float2*>(W + off);
    float2 v1 = *reinterpret_cast<const float2*>(W + off + 8);
    uint32_t h0, l0, h1, l1;
    split2(v0, h0, l0);
    split2(v1, h1, l1);
    uint4 o; o.x = h0; o.y = h1; o.z = l0; o.w = l1;
    *reinterpret_cast<uint4*>(g_whf + (size_t)id * 16) = o;
}

// ---------------------------------------------------------------------------
// Route kernel: 2-split fp16 mma argmax-GEMM, occupancy-exact partition,
// flat cross-unit cp.async pipeline (no drain bubble at unit boundaries).
// grid = 296 (2 CTAs/SM), block = 256. CTA i owns units [i*2048/296,(i+1)*2048/296).
// unit u: th = u>>3 (tile*32+head), chunk = u&7 (48 n-tiles = 6 groups).
// Partial argmax merged via atomicMax on packed u64.
// ---------------------------------------------------------------------------
__global__ __launch_bounds__(256, 2) void tc_route_kernel(const float* __restrict__ x)
{
    extern __shared__ uint8_t smem[];
    float* xs = reinterpret_cast<float*>(smem);
    const uint32_t sbB = s2u(smem) + SM_B;

    const int tid = threadIdx.x, lane = tid & 31, wid = tid >> 5;
    const int u0 = (int)(((long long)blockIdx.x * NUNIT) / NCTA);
    const int u1 = (int)(((long long)(blockIdx.x + 1) * NUNIT) / NCTA);
    const int ngrp = (u1 - u0) * (CHNT / GSZ);

    // stage group g (flat index) into buffer g&1; derives its own head/chunk
    auto stageg = [&](int g) {
        int u = u0 + g / (CHNT / GSZ);
        int gi = g % (CHNT / GSZ);
        int hd = (u >> 3) & 31, ch = u & 7;
        int F0 = ch * CHNT + gi * GSZ;
        int mat = F0 >> 7, ntl0 = F0 & (NTPM - 1);
        const uint8_t* src = g_whf
            + (((size_t)mat * NHEAD + hd) * NTPM + ntl0) * NT_B + tid * 16;
        uint32_t dst = sbB + (uint32_t)(g & 1) * GRP_B + tid * 16;
        #pragma unroll
        for (int j = 0; j < 4; ++j)
            cp16(dst + j * 4096u, src + (size_t)j * 4096);
    };

    uint32_t ah[2][4][4], al[2][4][4];
    int cur_th = -1;
    int head = 0, t0 = 0;

    float bmax[4]; int bidx[4];
    #pragma unroll
    for (int sl = 0; sl < 4; ++sl) { bmax[sl] = -3.402823466e38f; bidx[sl] = 0; }

    stageg(0); CP_COMMIT();

    #pragma unroll 1
    for (int g = 0; g < ngrp; ++g) {
        const int u = u0 + g / (CHNT / GSZ);
        const int th = u >> 3, chunk = u & 7, gi = g % (CHNT / GSZ);

        if (th != cur_th) {   // new (token-tile, head): restage x, rebuild A frags
            cur_th = th;
            head = th & 31;
            t0 = (th >> 5) * CTOK;
            __syncthreads();
            for (int i = tid; i < CTOK * 16; i += 256) {
                int t = i >> 4, c = i & 15;
                float4 v = *reinterpret_cast<const float4*>(
                    x + (size_t)(t0 + t) * CDIM + head * DDIM + c * 4);
                *reinterpret_cast<float4*>(&xs[t * SM_XPIT + c * 4]) = v;
            }
            __syncthreads();
            const int r0 = wid * 32 + (lane >> 2);
            #pragma unroll
            for (int mt = 0; mt < 2; ++mt)
                #pragma unroll
                for (int ks = 0; ks < 4; ++ks)
                    #pragma unroll
                    for (int e = 0; e < 4; ++e) {
                        int row = r0 + mt * 16 + (e & 1) * 8;
                        int kc  = ks * 16 + 2 * (lane & 3) + (e >> 1) * 8;
                        float2 v = *reinterpret_cast<const float2*>(
                            &xs[row * SM_XPIT + kc]);
                        split2(v, ah[mt][ks][e], al[mt][ks][e]);
                    }
        }

        if (g + 1 < ngrp) { stageg(g + 1); CP_COMMIT(); CP_WAIT1(); }
        else              { CP_WAIT0(); }
        __syncthreads();

        const uint32_t bb = sbB + (uint32_t)(g & 1) * GRP_B
                          + (uint32_t)lane * 16u;
        const int Fbase = chunk * CHNT + gi * GSZ;
        #pragma unroll 2
        for (int ntg = 0; ntg < GSZ; ++ntg) {
            const int F = Fbase + ntg;
            float d0[4] = {0.f, 0.f, 0.f, 0.f};
            float d1[4] = {0.f, 0.f, 0.f, 0.f};
            const uint32_t tb = bb + (uint32_t)ntg * NT_B;
            #pragma unroll
            for (int ks = 0; ks < 4; ++ks) {
                uint32_t bh0, bh1, bl0, bl1;
                asm volatile("ld.shared.v4.b32 {%0,%1,%2,%3}, [%4];"
                             : "=r"(bh0), "=r"(bh1), "=r"(bl0), "=r"(bl1)
                             : "r"(tb + ks * 512u));
                mma_f16(d0, ah[0][ks], bh0, bh1);   // hh
                mma_f16(d0, al[0][ks], bh0, bh1);   // lh
                mma_f16(d0, ah[0][ks], bl0, bl1);   // hl
                mma_f16(d1, ah[1][ks], bh0, bh1);
                mma_f16(d1, al[1][ks], bh0, bh1);
                mma_f16(d1, ah[1][ks], bl0, bl1);
            }
            const int cb = (F & (NTPM - 1)) * 8 + 2 * (lane & 3);
            if (d0[0] > bmax[0]) { bmax[0] = d0[0]; bidx[0] = cb; }
            if (d0[1] > bmax[0]) { bmax[0] = d0[1]; bidx[0] = cb + 1; }
            if (d0[2] > bmax[1]) { bmax[1] = d0[2]; bidx[1] = cb; }
            if (d0[3] > bmax[1]) { bmax[1] = d0[3]; bidx[1] = cb + 1; }
            if (d1[0] > bmax[2]) { bmax[2] = d1[0]; bidx[2] = cb; }
            if (d1[1] > bmax[2]) { bmax[2] = d1[1]; bidx[2] = cb + 1; }
            if (d1[2] > bmax[3]) { bmax[3] = d1[2]; bidx[3] = cb; }
            if (d1[3] > bmax[3]) { bmax[3] = d1[3]; bidx[3] = cb + 1; }

            // flush at matrix boundary or unit end (partials merged globally)
            if ((F & (NTPM - 1)) == NTPM - 1 || F == chunk * CHNT + CHNT - 1) {
                const int mat = F >> 7;
                unsigned long long* B =
                    g_best + ((size_t)mat * NHEAD + head) * TOK + t0;
                #pragma unroll
                for (int sl = 0; sl < 4; ++sl) {
                    float bv = bmax[sl]; int bi = bidx[sl];
                    #pragma unroll
                    for (int off = 1; off < 4; off <<= 1) {
                        float om = __shfl_xor_sync(0xffffffffu, bv, off, 32);
                        int   oi = __shfl_xor_sync(0xffffffffu, bi, off, 32);
                        if (om > bv || (om == bv && oi < bi)) {
                            bv = om; bi = oi;
                        }
                    }
                    if ((lane & 3) == 0) {
                        int row = wid * 32 + (lane >> 2)
                                + (sl >> 1) * 16 + (sl & 1) * 8;
                        atomicMax(&B[row], packcmp(bv, bi));
                    }
                    bmax[sl] = -3.402823466e38f; bidx[sl] = 0;
                }
            }
        }
        __syncthreads();
    }
}

// ---------------------------------------------------------------------------
// tau matching via bucketed counting sort; ids decoded from g_best.
// grid = NHEAD, block = 1024 (short serial chains per phase).
// ---------------------------------------------------------------------------
__global__ __launch_bounds__(1024) void match_kernel()
{
    __shared__ int cnt[KR];
    __shared__ int bstart[KR + 1];
    __shared__ int kpos[TOK];
    __shared__ int wsum[32];

    const int m = blockIdx.x, tid = threadIdx.x;
    const int lane = tid & 31, wid = tid >> 5;
    const unsigned long long* bq = g_best + (size_t)(0 * NHEAD + m) * TOK;
    const unsigned long long* bk = g_best + (size_t)(1 * NHEAD + m) * TOK;
    const unsigned long long* bv = g_best + (size_t)(2 * NHEAD + m) * TOK;

    cnt[tid] = 0;
    int k0 = unpack_col(bk[tid]);
    int k1 = unpack_col(bk[tid + 1024]);
    __syncthreads();
    atomicAdd(&cnt[k0], 1);
    atomicAdd(&cnt[k1], 1);
    __syncthreads();

    // exclusive prefix over 1024 counters, 1 per thread
    int c = cnt[tid];
    int incl = c;
    #pragma unroll
    for (int off = 1; off < 32; off <<= 1) {
        int nv = __shfl_up_sync(0xffffffffu, incl, off, 32);
        if (lane >= off) incl += nv;
    }
    if (lane == 31) wsum[wid] = incl;
    __syncthreads();
    if (wid == 0) {
        int v = wsum[lane];
        int wincl = v;
        #pragma unroll
        for (int off = 1; off < 32; off <<= 1) {
            int nv = __shfl_up_sync(0xffffffffu, wincl, off, 32);
            if (lane >= off) wincl += nv;
        }
        wsum[lane] = wincl - v;   // exclusive
    }
    __syncthreads();
    int ex = incl - c + wsum[wid];
    bstart[tid] = ex;
    if (tid == 0) bstart[KR] = TOK;
    __syncthreads();
    cnt[tid] = ex;   // scatter cursor
    __syncthreads();

    {
        int p = atomicAdd(&cnt[k0], 1);
        kpos[p] = tid;
        int p1 = atomicAdd(&cnt[k1], 1);
        kpos[p1] = tid + 1024;
    }
    __syncthreads();

    // sort each bucket ascending (1 bucket per thread, avg size 2)
    {
        int lo = bstart[tid], hi = bstart[tid + 1];
        for (int i = lo + 1; i < hi; ++i) {
            int v = kpos[i], j = i - 1;
            while (j >= lo && kpos[j] > v) { kpos[j + 1] = kpos[j]; --j; }
            kpos[j + 1] = v;
        }
    }
    __syncthreads();

    #pragma unroll
    for (int h = 0; h < 2; ++h) {
        int t = tid + h * 1024;
        int q = unpack_col(bq[t]);
        int lo = bstart[q], hi = bstart[q + 1];
        int best = -1;
        for (int i = hi - 1; i >= lo; --i) {
            if (kpos[i] < t) { best = kpos[i]; break; }
        }
        g_row[m * TOK + t] = (best >= 0) ? (unpack_col(bv[best]) + 1) : 0;
    }
}

// ---------------------------------------------------------------------------
// Embedding gather. grid = (TOK/128, NHEAD) = (16, 32), block = 256.
// Rows staged to smem once; 8 independent float4 gathers per thread (MLP 8).
// ---------------------------------------------------------------------------
__global__ __launch_bounds__(256) void gather_kernel(
    const float* __restrict__ emb, float* __restrict__ out)
{
    __shared__ int rows[128];
    const int m = blockIdx.y, t0 = blockIdx.x * 128;
    const int tid = threadIdx.x;
    if (tid < 128) rows[tid] = g_row[m * TOK + t0 + tid];
    __syncthreads();
    const float* E = emb + (size_t)m * (KR + 1) * DDIM;
    #pragma unroll
    for (int it = 0; it < 8; ++it) {
        int j = tid + it * 256;
        int t = j >> 4, dg = j & 15;
        int row = rows[t];
        float4 v;
        if (row) {
            v = *reinterpret_cast<const float4*>(E + (size_t)row * DDIM + dg * 4);
        } else {
            v = make_float4(0.f, 0.f, 0.f, 0.f);   // padding row is zero
        }
        *reinterpret_cast<float4*>(out + (size_t)(t0 + t) * CDIM + m * DDIM + dg * 4) = v;
    }
}

// ---------------------------------------------------------------------------
extern "C" void kernel_launch(void* const* d_in, const int* in_sizes, int n_in,
                              void* d_out, int out_size)
{
    (void)in_sizes; (void)n_in; (void)out_size;
    const float* x   = (const float*)d_in[0];
    const float* wq  = (const float*)d_in[1];
    const float* wk  = (const float*)d_in[2];
    const float* wv  = (const float*)d_in[3];
    const float* emb = (const float*)d_in[4];
    float* out = (float*)d_out;

    cudaFuncSetAttribute(tc_route_kernel,
                         cudaFuncAttributeMaxDynamicSharedMemorySize, SM_TOTAL);

    split_w_kernel<<<(3 * NHEAD * NTPM * 4 * 32) / 256, 256>>>(wq, wk, wv);
    tc_route_kernel<<<NCTA, 256, SM_TOTAL>>>(x);
    match_kernel<<<NHEAD, 1024>>>();
    dim3 g3(TOK / 128, NHEAD);
    gather_kernel<<<g3, 256>>>(emb, out);
}

// round 14
// speedup vs baseline: 1.0258x; 1.0258x over previous
#include <cuda_runtime.h>
#include <cuda_fp16.h>
#include <cstdint>

#define TOK   2048
#define CDIM  2048
#define NHEAD 32
#define DDIM  64
#define KR    1024

#define CTOK  256            // tokens per x tile
#define NTPM  128            // 8-col n-tiles per matrix
#define GSZ   8              // n-tiles per pipeline group
#define CHNT  48             // n-tiles per work unit (6 groups)
#define NUNIT 2048           // 8 tiles x 32 heads x 8 chunks
#define NCTA  296            // exactly 2 CTAs per SM on 148 SMs
#define NT_B  2048           // bytes per n-tile (hi/lo interleaved 16B)
#define GRP_B (GSZ * NT_B)   // 16 KB

#define SM_XPIT 68
#define SM_B    (CTOK * SM_XPIT * 4)          // 69632
#define SM_TOTAL (SM_B + 2 * GRP_B)           // 102400 -> 2 CTAs/SM

__device__ int g_row[NHEAD * TOK];
__device__ unsigned long long g_best[(size_t)3 * NHEAD * TOK];
// W fp16 hi/lo interleaved, fragment-major: [mat][head][ntl][ks][lane]{h0,h1,l0,l1}
__device__ __align__(16) uint8_t g_whf[(size_t)3 * NHEAD * NTPM * NT_B];   // 24 MB

// ---------------- helpers ----------------
static __device__ __forceinline__ uint32_t s2u(const void* p) {
    uint32_t a;
    asm("{ .reg .u64 t; cvta.to.shared.u64 t, %1; cvt.u32.u64 %0, t; }"
        : "=r"(a) : "l"(p));
    return a;
}
static __device__ __forceinline__ uint32_t h2u(__half2 h) {
    uint32_t u; asm("mov.b32 %0, %1;" : "=r"(u) : "r"(*(uint32_t*)&h)); return u;
}
static __device__ __forceinline__ void mma_f16(float* d, const uint32_t* a,
                                               uint32_t b0, uint32_t b1) {
    asm volatile("mma.sync.aligned.m16n8k16.row.col.f32.f16.f16.f32 "
                 "{%0,%1,%2,%3}, {%4,%5,%6,%7}, {%8,%9}, {%0,%1,%2,%3};"
                 : "+f"(d[0]), "+f"(d[1]), "+f"(d[2]), "+f"(d[3])
                 : "r"(a[0]), "r"(a[1]), "r"(a[2]), "r"(a[3]),
                   "r"(b0), "r"(b1));
}
static __device__ __forceinline__ void cp16(uint32_t d, const void* s) {
    asm volatile("cp.async.cg.shared.global [%0], [%1], 16;"
                 :: "r"(d), "l"(s) : "memory");
}
#define CP_COMMIT() asm volatile("cp.async.commit_group;" ::: "memory")
#define CP_WAIT1()  asm volatile("cp.async.wait_group 1;" ::: "memory")
#define CP_WAIT0()  asm volatile("cp.async.wait_group 0;" ::: "memory")

// split one float pair into packed fp16 hi / lo
static __device__ __forceinline__ void split2(float2 v, uint32_t& h, uint32_t& l) {
    __half2 hh = __float22half2_rn(v);
    float2 hf = __half22float2(hh);
    __half2 ll = __float22half2_rn(make_float2(v.x - hf.x, v.y - hf.y));
    h = h2u(hh); l = h2u(ll);
}
// orderable packing: larger logit wins; tie -> smaller col wins; 0 < any real
static __device__ __forceinline__ unsigned long long packcmp(float v, int col) {
    uint32_t b = __float_as_uint(v);
    uint32_t u = (b & 0x80000000u) ? ~b : (b | 0x80000000u);
    return ((unsigned long long)u << 32)
         | (unsigned long long)(0xFFFFFFFFu - (uint32_t)col);
}
static __device__ __forceinline__ int unpack_col(unsigned long long p) {
    return (int)(0xFFFFFFFFu - (uint32_t)(p & 0xFFFFFFFFull));
}

// ---------------------------------------------------------------------------
// Prepass: split W into fp16 hi/lo, fragment-major, hi/lo interleaved 16B.
// id bits: lane[0:5) ks[5:7) ntl[7:14) head[14:19) mat[19:21)
// Also zeroes g_best (first 196608 threads).
// ---------------------------------------------------------------------------
__global__ __launch_bounds__(256) void split_w_kernel(
    const float* __restrict__ wq, const float* __restrict__ wk,
    const float* __restrict__ wv)
{
    uint32_t id = blockIdx.x * 256u + threadIdx.x;
    if (id < 3u * NHEAD * TOK) g_best[id] = 0ull;
    uint32_t lane = id & 31u;
    uint32_t ks   = (id >> 5) & 3u;
    uint32_t ntl  = (id >> 7) & 127u;
    uint32_t head = (id >> 14) & 31u;
    uint32_t mat  = id >> 19;
    const float* W = (mat == 0) ? wq : (mat == 1) ? wk : wv;
    int col = (int)(ntl * 8 + (lane >> 2));
    int k0  = (int)(ks * 16 + 2 * (lane & 3));
    size_t off = ((size_t)head * KR + col) * DDIM + k0;
    float2 v0 = *reinterpret_cast<const float2*>(W + off);
    float2 v1 = *reinterpret_cast<const float2*>(W + off + 8);
    uint32_t h0, l0, h1, l1;
    split2(v0, h0, l0);
    split2(v1, h1, l1);
    uint4 o; o.x = h0; o.y = h1; o.z = l0; o.w = l1;
    *reinterpret_cast<uint4*>(g_whf + (size_t)id * 16) = o;
}

// ---------------------------------------------------------------------------
// Route kernel: 2-split fp16 mma argmax-GEMM, occupancy-exact partition.
// grid = 296 (2 CTAs/SM), block = 256. CTA i owns units [i*2048/296,(i+1)*2048/296).
// unit u: t8 = u>>8, head = (u>>3)&31, chunk = u&7 (48 n-tiles).
// Partial argmax merged via atomicMax on packed u64.
// ---------------------------------------------------------------------------
__global__ __launch_bounds__(256, 2) void tc_route_kernel(const float* __restrict__ x)
{
    extern __shared__ uint8_t smem[];
    float* xs = reinterpret_cast<float*>(smem);
    const uint32_t sbB = s2u(smem) + SM_B;

    const int tid = threadIdx.x, lane = tid & 31, wid = tid >> 5;
    const int u0 = (int)(((long long)blockIdx.x * NUNIT) / NCTA);
    const int u1 = (int)(((long long)(blockIdx.x + 1) * NUNIT) / NCTA);

    uint32_t ah[2][4][4], al[2][4][4];
    int cur_th = -1;
    int head = 0, t0 = 0;

    float bmax[4]; int bidx[4];
    #pragma unroll
    for (int sl = 0; sl < 4; ++sl) { bmax[sl] = -3.402823466e38f; bidx[sl] = 0; }

    for (int u = u0; u < u1; ++u) {
        const int th = u >> 3;
        const int chunk = u & 7;
        if (th != cur_th) {
            cur_th = th;
            head = th & 31;
            t0 = (th >> 5) * CTOK;
            __syncthreads();   // all warps done with previous compute / xs reads
            for (int i = tid; i < CTOK * 16; i += 256) {
                int t = i >> 4, c = i & 15;
                float4 v = *reinterpret_cast<const float4*>(
                    x + (size_t)(t0 + t) * CDIM + head * DDIM + c * 4);
                *reinterpret_cast<float4*>(&xs[t * SM_XPIT + c * 4]) = v;
            }
            __syncthreads();
            const int r0 = wid * 32 + (lane >> 2);
            #pragma unroll
            for (int mt = 0; mt < 2; ++mt)
                #pragma unroll
                for (int ks = 0; ks < 4; ++ks)
                    #pragma unroll
                    for (int e = 0; e < 4; ++e) {
                        int row = r0 + mt * 16 + (e & 1) * 8;
                        int kc  = ks * 16 + 2 * (lane & 3) + (e >> 1) * 8;
                        float2 v = *reinterpret_cast<const float2*>(
                            &xs[row * SM_XPIT + kc]);
                        split2(v, ah[mt][ks][e], al[mt][ks][e]);
                    }
        }

        const int F0u = chunk * CHNT;
        auto stage = [&](int gi) {
            int F0 = F0u + gi * GSZ;
            int mat = F0 >> 7, ntl0 = F0 & (NTPM - 1);
            const uint8_t* src = g_whf
                + (((size_t)mat * NHEAD + head) * NTPM + ntl0) * NT_B + tid * 16;
            uint32_t dst = sbB + (uint32_t)(gi & 1) * GRP_B + tid * 16;
            #pragma unroll
            for (int j = 0; j < 4; ++j)
                cp16(dst + j * 4096u, src + (size_t)j * 4096);
        };

        stage(0); CP_COMMIT();

        #pragma unroll 1
        for (int gi = 0; gi < CHNT / GSZ; ++gi) {
            if (gi + 1 < CHNT / GSZ) { stage(gi + 1); CP_COMMIT(); CP_WAIT1(); }
            else                     { CP_WAIT0(); }
            __syncthreads();

            const uint32_t bb = sbB + (uint32_t)(gi & 1) * GRP_B
                              + (uint32_t)lane * 16u;
            #pragma unroll 2
            for (int ntg = 0; ntg < GSZ; ++ntg) {
                const int F = F0u + gi * GSZ + ntg;
                float d0[4] = {0.f, 0.f, 0.f, 0.f};
                float d1[4] = {0.f, 0.f, 0.f, 0.f};
                const uint32_t tb = bb + (uint32_t)ntg * NT_B;
                #pragma unroll
                for (int ks = 0; ks < 4; ++ks) {
                    uint32_t bh0, bh1, bl0, bl1;
                    asm volatile("ld.shared.v4.b32 {%0,%1,%2,%3}, [%4];"
                                 : "=r"(bh0), "=r"(bh1), "=r"(bl0), "=r"(bl1)
                                 : "r"(tb + ks * 512u));
                    mma_f16(d0, ah[0][ks], bh0, bh1);   // hh
                    mma_f16(d0, al[0][ks], bh0, bh1);   // lh
                    mma_f16(d0, ah[0][ks], bl0, bl1);   // hl
                    mma_f16(d1, ah[1][ks], bh0, bh1);
                    mma_f16(d1, al[1][ks], bh0, bh1);
                    mma_f16(d1, ah[1][ks], bl0, bl1);
                }
                const int cb = (F & (NTPM - 1)) * 8 + 2 * (lane & 3);
                if (d0[0] > bmax[0]) { bmax[0] = d0[0]; bidx[0] = cb; }
                if (d0[1] > bmax[0]) { bmax[0] = d0[1]; bidx[0] = cb + 1; }
                if (d0[2] > bmax[1]) { bmax[1] = d0[2]; bidx[1] = cb; }
                if (d0[3] > bmax[1]) { bmax[1] = d0[3]; bidx[1] = cb + 1; }
                if (d1[0] > bmax[2]) { bmax[2] = d1[0]; bidx[2] = cb; }
                if (d1[1] > bmax[2]) { bmax[2] = d1[1]; bidx[2] = cb + 1; }
                if (d1[2] > bmax[3]) { bmax[3] = d1[2]; bidx[3] = cb; }
                if (d1[3] > bmax[3]) { bmax[3] = d1[3]; bidx[3] = cb + 1; }

                // flush at matrix boundary or unit end
                if ((F & (NTPM - 1)) == NTPM - 1 || F == F0u + CHNT - 1) {
                    const int mat = F >> 7;
                    unsigned long long* B =
                        g_best + ((size_t)mat * NHEAD + head) * TOK + t0;
                    #pragma unroll
                    for (int sl = 0; sl < 4; ++sl) {
                        float bv = bmax[sl]; int bi = bidx[sl];
                        #pragma unroll
                        for (int off = 1; off < 4; off <<= 1) {
                            float om = __shfl_xor_sync(0xffffffffu, bv, off, 32);
                            int   oi = __shfl_xor_sync(0xffffffffu, bi, off, 32);
                            if (om > bv || (om == bv && oi < bi)) {
                                bv = om; bi = oi;
                            }
                        }
                        if ((lane & 3) == 0) {
                            int row = wid * 32 + (lane >> 2)
                                    + (sl >> 1) * 16 + (sl & 1) * 8;
                            atomicMax(&B[row], packcmp(bv, bi));
                        }
                        bmax[sl] = -3.402823466e38f; bidx[sl] = 0;
                    }
                }
            }
            __syncthreads();
        }
    }
}

// ---------------------------------------------------------------------------
// tau matching via bucketed counting sort; ids decoded from g_best.
// grid = NHEAD, block = 1024 (short serial chains per phase).
// ---------------------------------------------------------------------------
__global__ __launch_bounds__(1024) void match_kernel()
{
    __shared__ int cnt[KR];
    __shared__ int bstart[KR + 1];
    __shared__ int kpos[TOK];
    __shared__ int wsum[32];

    const int m = blockIdx.x, tid = threadIdx.x;
    const int lane = tid & 31, wid = tid >> 5;
    const unsigned long long* bq = g_best + (size_t)(0 * NHEAD + m) * TOK;
    const unsigned long long* bk = g_best + (size_t)(1 * NHEAD + m) * TOK;
    const unsigned long long* bv = g_best + (size_t)(2 * NHEAD + m) * TOK;

    cnt[tid] = 0;
    int k0 = unpack_col(bk[tid]);
    int k1 = unpack_col(bk[tid + 1024]);
    __syncthreads();
    atomicAdd(&cnt[k0], 1);
    atomicAdd(&cnt[k1], 1);
    __syncthreads();

    // exclusive prefix over 1024 counters, 1 per thread
    int c = cnt[tid];
    int incl = c;
    #pragma unroll
    for (int off = 1; off < 32; off <<= 1) {
        int nv = __shfl_up_sync(0xffffffffu, incl, off, 32);
        if (lane >= off) incl += nv;
    }
    if (lane == 31) wsum[wid] = incl;
    __syncthreads();
    if (wid == 0) {
        int v = wsum[lane];
        int wincl = v;
        #pragma unroll
        for (int off = 1; off < 32; off <<= 1) {
            int nv = __shfl_up_sync(0xffffffffu, wincl, off, 32);
            if (lane >= off) wincl += nv;
        }
        wsum[lane] = wincl - v;   // exclusive
    }
    __syncthreads();
    int ex = incl - c + wsum[wid];
    bstart[tid] = ex;
    if (tid == 0) bstart[KR] = TOK;
    __syncthreads();
    cnt[tid] = ex;   // scatter cursor
    __syncthreads();

    {
        int p = atomicAdd(&cnt[k0], 1);
        kpos[p] = tid;
        int p1 = atomicAdd(&cnt[k1], 1);
        kpos[p1] = tid + 1024;
    }
    __syncthreads();

    // sort each bucket ascending (1 bucket per thread, avg size 2)
    {
        int lo = bstart[tid], hi = bstart[tid + 1];
        for (int i = lo + 1; i < hi; ++i) {
            int v = kpos[i], j = i - 1;
            while (j >= lo && kpos[j] > v) { kpos[j + 1] = kpos[j]; --j; }
            kpos[j + 1] = v;
        }
    }
    __syncthreads();

    #pragma unroll
    for (int h = 0; h < 2; ++h) {
        int t = tid + h * 1024;
        int q = unpack_col(bq[t]);
        int lo = bstart[q], hi = bstart[q + 1];
        int best = -1;
        for (int i = hi - 1; i >= lo; --i) {
            if (kpos[i] < t) { best = kpos[i]; break; }
        }
        g_row[m * TOK + t] = (best >= 0) ? (unpack_col(bv[best]) + 1) : 0;
    }
}

// ---------------------------------------------------------------------------
// Embedding gather. grid = (TOK/64, NHEAD) = (32, 32), block = 256.
// Rows staged to smem once (no redundant g_row loads, no dependent chains);
// each thread then issues 4 independent gather float4s (MLP 4).
// ---------------------------------------------------------------------------
__global__ __launch_bounds__(256) void gather_kernel(
    const float* __restrict__ emb, float* __restrict__ out)
{
    __shared__ int rows[64];
    const int m = blockIdx.y, t0 = blockIdx.x * 64;
    const int tid = threadIdx.x;
    if (tid < 64) rows[tid] = g_row[m * TOK + t0 + tid];
    __syncthreads();
    const float* E = emb + (size_t)m * (KR + 1) * DDIM;
    #pragma unroll
    for (int it = 0; it < 4; ++it) {
        int j = tid + it * 256;
        int t = j >> 4, dg = j & 15;
        int row = rows[t];
        float4 v;
        if (row) {
            v = *reinterpret_cast<const float4*>(E + (size_t)row * DDIM + dg * 4);
        } else {
            v = make_float4(0.f, 0.f, 0.f, 0.f);   // padding row is zero
        }
        *reinterpret_cast<float4*>(out + (size_t)(t0 + t) * CDIM + m * DDIM + dg * 4) = v;
    }
}

// ---------------------------------------------------------------------------
extern "C" void kernel_launch(void* const* d_in, const int* in_sizes, int n_in,
                              void* d_out, int out_size)
{
    (void)in_sizes; (void)n_in; (void)out_size;
    const float* x   = (const float*)d_in[0];
    const float* wq  = (const float*)d_in[1];
    const float* wk  = (const float*)d_in[2];
    const float* wv  = (const float*)d_in[3];
    const float* emb = (const float*)d_in[4];
    float* out = (float*)d_out;

    cudaFuncSetAttribute(tc_route_kernel,
                         cudaFuncAttributeMaxDynamicSharedMemorySize, SM_TOTAL);

    split_w_kernel<<<(3 * NHEAD * NTPM * 4 * 32) / 256, 256>>>(wq, wk, wv);
    tc_route_kernel<<<NCTA, 256, SM_TOTAL>>>(x);
    match_kernel<<<NHEAD, 1024>>>();
    dim3 g3(TOK / 64, NHEAD);
    gather_kernel<<<g3, 256>>>(emb, out);
}

// round 15
// speedup vs baseline: 1.0321x; 1.0061x over previous
#include <cuda_runtime.h>
#include <cuda_fp16.h>
#include <cstdint>

#define TOK   2048
#define CDIM  2048
#define NHEAD 32
#define DDIM  64
#define KR    1024

#define CTOK  256            // tokens per x tile
#define NTPM  128            // 8-col n-tiles per matrix
#define GSZ   8              // n-tiles per pipeline group
#define CHNT  48             // n-tiles per work unit (6 groups)
#define NUNIT 2048           // 8 tiles x 32 heads x 8 chunks
#define NCTA  296            // exactly 2 CTAs per SM on 148 SMs
#define NT_B  2048           // bytes per n-tile (hi/lo interleaved 16B)
#define GRP_B (GSZ * NT_B)   // 16 KB

#define SM_XPIT 68
#define SM_B    (CTOK * SM_XPIT * 4)          // 69632
#define SM_TOTAL (SM_B + 2 * GRP_B)           // 102400 -> 2 CTAs/SM

__device__ int g_row[NHEAD * TOK];
__device__ unsigned long long g_best[(size_t)3 * NHEAD * TOK];
// W fp16 hi/lo interleaved, fragment-major: [mat][head][ntl][ks][lane]{h0,h1,l0,l1}
__device__ __align__(16) uint8_t g_whf[(size_t)3 * NHEAD * NTPM * NT_B];   // 24 MB

// ---------------- helpers ----------------
static __device__ __forceinline__ uint32_t s2u(const void* p) {
    uint32_t a;
    asm("{ .reg .u64 t; cvta.to.shared.u64 t, %1; cvt.u32.u64 %0, t; }"
        : "=r"(a) : "l"(p));
    return a;
}
static __device__ __forceinline__ uint32_t h2u(__half2 h) {
    uint32_t u; asm("mov.b32 %0, %1;" : "=r"(u) : "r"(*(uint32_t*)&h)); return u;
}
static __device__ __forceinline__ void mma_f16(float* d, const uint32_t* a,
                                               uint32_t b0, uint32_t b1) {
    asm volatile("mma.sync.aligned.m16n8k16.row.col.f32.f16.f16.f32 "
                 "{%0,%1,%2,%3}, {%4,%5,%6,%7}, {%8,%9}, {%0,%1,%2,%3};"
                 : "+f"(d[0]), "+f"(d[1]), "+f"(d[2]), "+f"(d[3])
                 : "r"(a[0]), "r"(a[1]), "r"(a[2]), "r"(a[3]),
                   "r"(b0), "r"(b1));
}
static __device__ __forceinline__ void cp16(uint32_t d, const void* s) {
    asm volatile("cp.async.cg.shared.global [%0], [%1], 16;"
                 :: "r"(d), "l"(s) : "memory");
}
#define CP_COMMIT() asm volatile("cp.async.commit_group;" ::: "memory")
#define CP_WAIT1()  asm volatile("cp.async.wait_group 1;" ::: "memory")
#define CP_WAIT0()  asm volatile("cp.async.wait_group 0;" ::: "memory")

// split one float pair into packed fp16 hi / lo
static __device__ __forceinline__ void split2(float2 v, uint32_t& h, uint32_t& l) {
    __half2 hh = __float22half2_rn(v);
    float2 hf = __half22float2(hh);
    __half2 ll = __float22half2_rn(make_float2(v.x - hf.x, v.y - hf.y));
    h = h2u(hh); l = h2u(ll);
}
// orderable packing: larger logit wins; tie -> smaller col wins; 0 < any real
static __device__ __forceinline__ unsigned long long packcmp(float v, int col) {
    uint32_t b = __float_as_uint(v);
    uint32_t u = (b & 0x80000000u) ? ~b : (b | 0x80000000u);
    return ((unsigned long long)u << 32)
         | (unsigned long long)(0xFFFFFFFFu - (uint32_t)col);
}
static __device__ __forceinline__ int unpack_col(unsigned long long p) {
    return (int)(0xFFFFFFFFu - (uint32_t)(p & 0xFFFFFFFFull));
}

// ---------------------------------------------------------------------------
// Prepass: split W into fp16 hi/lo, fragment-major, hi/lo interleaved 16B.
// id bits: lane[0:5) ks[5:7) ntl[7:14) head[14:19) mat[19:21)
// Also zeroes g_best (first 196608 threads).
// ---------------------------------------------------------------------------
__global__ __launch_bounds__(256) void split_w_kernel(
    const float* __restrict__ wq, const float* __restrict__ wk,
    const float* __restrict__ wv)
{
    uint32_t id = blockIdx.x * 256u + threadIdx.x;
    if (id < 3u * NHEAD * TOK) g_best[id] = 0ull;
    uint32_t lane = id & 31u;
    uint32_t ks   = (id >> 5) & 3u;
    uint32_t ntl  = (id >> 7) & 127u;
    uint32_t head = (id >> 14) & 31u;
    uint32_t mat  = id >> 19;
    const float* W = (mat == 0) ? wq : (mat == 1) ? wk : wv;
    int col = (int)(ntl * 8 + (lane >> 2));
    int k0  = (int)(ks * 16 + 2 * (lane & 3));
    size_t off = ((size_t)head * KR + col) * DDIM + k0;
    float2 v0 = *reinterpret_cast<const float2*>(W + off);
    float2 v1 = *reinterpret_cast<const float2*>(W + off + 8);
    uint32_t h0, l0, h1, l1;
    split2(v0, h0, l0);
    split2(v1, h1, l1);
    uint4 o; o.x = h0; o.y = h1; o.z = l0; o.w = l1;
    *reinterpret_cast<uint4*>(g_whf + (size_t)id * 16) = o;
}

// ---------------------------------------------------------------------------
// Route kernel: 2-split fp16 mma argmax-GEMM, occupancy-exact partition.
// grid = 296 (2 CTAs/SM), block = 256. CTA i owns units [i*2048/296,(i+1)*2048/296).
// unit u: t8 = u>>8, head = (u>>3)&31, chunk = u&7 (48 n-tiles).
// Partial argmax merged via atomicMax on packed u64.
// ---------------------------------------------------------------------------
__global__ __launch_bounds__(256, 2) void tc_route_kernel(const float* __restrict__ x)
{
    extern __shared__ uint8_t smem[];
    float* xs = reinterpret_cast<float*>(smem);
    const uint32_t sbB = s2u(smem) + SM_B;

    const int tid = threadIdx.x, lane = tid & 31, wid = tid >> 5;
    const int u0 = (int)(((long long)blockIdx.x * NUNIT) / NCTA);
    const int u1 = (int)(((long long)(blockIdx.x + 1) * NUNIT) / NCTA);

    uint32_t ah[2][4][4], al[2][4][4];
    int cur_th = -1;
    int head = 0, t0 = 0;

    float bmax[4]; int bidx[4];
    #pragma unroll
    for (int sl = 0; sl < 4; ++sl) { bmax[sl] = -3.402823466e38f; bidx[sl] = 0; }

    for (int u = u0; u < u1; ++u) {
        const int th = u >> 3;
        const int chunk = u & 7;
        if (th != cur_th) {
            cur_th = th;
            head = th & 31;
            t0 = (th >> 5) * CTOK;
            __syncthreads();   // all warps done with previous compute / xs reads
            for (int i = tid; i < CTOK * 16; i += 256) {
                int t = i >> 4, c = i & 15;
                float4 v = *reinterpret_cast<const float4*>(
                    x + (size_t)(t0 + t) * CDIM + head * DDIM + c * 4);
                *reinterpret_cast<float4*>(&xs[t * SM_XPIT + c * 4]) = v;
            }
            __syncthreads();
            const int r0 = wid * 32 + (lane >> 2);
            #pragma unroll
            for (int mt = 0; mt < 2; ++mt)
                #pragma unroll
                for (int ks = 0; ks < 4; ++ks)
                    #pragma unroll
                    for (int e = 0; e < 4; ++e) {
                        int row = r0 + mt * 16 + (e & 1) * 8;
                        int kc  = ks * 16 + 2 * (lane & 3) + (e >> 1) * 8;
                        float2 v = *reinterpret_cast<const float2*>(
                            &xs[row * SM_XPIT + kc]);
                        split2(v, ah[mt][ks][e], al[mt][ks][e]);
                    }
        }

        const int F0u = chunk * CHNT;
        auto stage = [&](int gi) {
            int F0 = F0u + gi * GSZ;
            int mat = F0 >> 7, ntl0 = F0 & (NTPM - 1);
            const uint8_t* src = g_whf
                + (((size_t)mat * NHEAD + head) * NTPM + ntl0) * NT_B + tid * 16;
            uint32_t dst = sbB + (uint32_t)(gi & 1) * GRP_B + tid * 16;
            #pragma unroll
            for (int j = 0; j < 4; ++j)
                cp16(dst + j * 4096u, src + (size_t)j * 4096);
        };

        stage(0); CP_COMMIT();

        #pragma unroll 1
        for (int gi = 0; gi < CHNT / GSZ; ++gi) {
            if (gi + 1 < CHNT / GSZ) { stage(gi + 1); CP_COMMIT(); CP_WAIT1(); }
            else                     { CP_WAIT0(); }
            __syncthreads();

            const uint32_t bb = sbB + (uint32_t)(gi & 1) * GRP_B
                              + (uint32_t)lane * 16u;
            #pragma unroll 2
            for (int ntg = 0; ntg < GSZ; ++ntg) {
                const int F = F0u + gi * GSZ + ntg;
                float d0[4] = {0.f, 0.f, 0.f, 0.f};
                float d1[4] = {0.f, 0.f, 0.f, 0.f};
                const uint32_t tb = bb + (uint32_t)ntg * NT_B;
                #pragma unroll
                for (int ks = 0; ks < 4; ++ks) {
                    uint32_t bh0, bh1, bl0, bl1;
                    asm volatile("ld.shared.v4.b32 {%0,%1,%2,%3}, [%4];"
                                 : "=r"(bh0), "=r"(bh1), "=r"(bl0), "=r"(bl1)
                                 : "r"(tb + ks * 512u));
                    mma_f16(d0, ah[0][ks], bh0, bh1);   // hh
                    mma_f16(d0, al[0][ks], bh0, bh1);   // lh
                    mma_f16(d0, ah[0][ks], bl0, bl1);   // hl
                    mma_f16(d1, ah[1][ks], bh0, bh1);
                    mma_f16(d1, al[1][ks], bh0, bh1);
                    mma_f16(d1, ah[1][ks], bl0, bl1);
                }
                const int cb = (F & (NTPM - 1)) * 8 + 2 * (lane & 3);
                if (d0[0] > bmax[0]) { bmax[0] = d0[0]; bidx[0] = cb; }
                if (d0[1] > bmax[0]) { bmax[0] = d0[1]; bidx[0] = cb + 1; }
                if (d0[2] > bmax[1]) { bmax[1] = d0[2]; bidx[1] = cb; }
                if (d0[3] > bmax[1]) { bmax[1] = d0[3]; bidx[1] = cb + 1; }
                if (d1[0] > bmax[2]) { bmax[2] = d1[0]; bidx[2] = cb; }
                if (d1[1] > bmax[2]) { bmax[2] = d1[1]; bidx[2] = cb + 1; }
                if (d1[2] > bmax[3]) { bmax[3] = d1[2]; bidx[3] = cb; }
                if (d1[3] > bmax[3]) { bmax[3] = d1[3]; bidx[3] = cb + 1; }

                // flush at matrix boundary or unit end
                if ((F & (NTPM - 1)) == NTPM - 1 || F == F0u + CHNT - 1) {
                    const int mat = F >> 7;
                    unsigned long long* B =
                        g_best + ((size_t)mat * NHEAD + head) * TOK + t0;
                    #pragma unroll
                    for (int sl = 0; sl < 4; ++sl) {
                        float bv = bmax[sl]; int bi = bidx[sl];
                        #pragma unroll
                        for (int off = 1; off < 4; off <<= 1) {
                            float om = __shfl_xor_sync(0xffffffffu, bv, off, 32);
                            int   oi = __shfl_xor_sync(0xffffffffu, bi, off, 32);
                            if (om > bv || (om == bv && oi < bi)) {
                                bv = om; bi = oi;
                            }
                        }
                        if ((lane & 3) == 0) {
                            int row = wid * 32 + (lane >> 2)
                                    + (sl >> 1) * 16 + (sl & 1) * 8;
                            atomicMax(&B[row], packcmp(bv, bi));
                        }
                        bmax[sl] = -3.402823466e38f; bidx[sl] = 0;
                    }
                }
            }
            __syncthreads();
        }
    }
}

// ---------------------------------------------------------------------------
// tau matching via bucketed counting sort; ids decoded from g_best.
// grid = NHEAD, block = 1024 (short serial chains per phase).
// ---------------------------------------------------------------------------
__global__ __launch_bounds__(1024) void match_kernel()
{
    __shared__ int cnt[KR];
    __shared__ int bstart[KR + 1];
    __shared__ int kpos[TOK];
    __shared__ int wsum[32];

    const int m = blockIdx.x, tid = threadIdx.x;
    const int lane = tid & 31, wid = tid >> 5;
    const unsigned long long* bq = g_best + (size_t)(0 * NHEAD + m) * TOK;
    const unsigned long long* bk = g_best + (size_t)(1 * NHEAD + m) * TOK;
    const unsigned long long* bv = g_best + (size_t)(2 * NHEAD + m) * TOK;

    cnt[tid] = 0;
    int k0 = unpack_col(bk[tid]);
    int k1 = unpack_col(bk[tid + 1024]);
    __syncthreads();
    atomicAdd(&cnt[k0], 1);
    atomicAdd(&cnt[k1], 1);
    __syncthreads();

    // exclusive prefix over 1024 counters, 1 per thread
    int c = cnt[tid];
    int incl = c;
    #pragma unroll
    for (int off = 1; off < 32; off <<= 1) {
        int nv = __shfl_up_sync(0xffffffffu, incl, off, 32);
        if (lane >= off) incl += nv;
    }
    if (lane == 31) wsum[wid] = incl;
    __syncthreads();
    if (wid == 0) {
        int v = wsum[lane];
        int wincl = v;
        #pragma unroll
        for (int off = 1; off < 32; off <<= 1) {
            int nv = __shfl_up_sync(0xffffffffu, wincl, off, 32);
            if (lane >= off) wincl += nv;
        }
        wsum[lane] = wincl - v;   // exclusive
    }
    __syncthreads();
    int ex = incl - c + wsum[wid];
    bstart[tid] = ex;
    if (tid == 0) bstart[KR] = TOK;
    __syncthreads();
    cnt[tid] = ex;   // scatter cursor
    __syncthreads();

    {
        int p = atomicAdd(&cnt[k0], 1);
        kpos[p] = tid;
        int p1 = atomicAdd(&cnt[k1], 1);
        kpos[p1] = tid + 1024;
    }
    __syncthreads();

    // sort each bucket ascending (1 bucket per thread, avg size 2)
    {
        int lo = bstart[tid], hi = bstart[tid + 1];
        for (int i = lo + 1; i < hi; ++i) {
            int v = kpos[i], j = i - 1;
            while (j >= lo && kpos[j] > v) { kpos[j + 1] = kpos[j]; --j; }
            kpos[j + 1] = v;
        }
    }
    __syncthreads();

    #pragma unroll
    for (int h = 0; h < 2; ++h) {
        int t = tid + h * 1024;
        int q = unpack_col(bq[t]);
        int lo = bstart[q], hi = bstart[q + 1];
        int best = -1;
        for (int i = hi - 1; i >= lo; --i) {
            if (kpos[i] < t) { best = kpos[i]; break; }
        }
        g_row[m * TOK + t] = (best >= 0) ? (unpack_col(bv[best]) + 1) : 0;
    }
}

// ---------------------------------------------------------------------------
// Embedding gather. grid = (TOK/64, NHEAD) = (32, 32), block = 256.
// Rows staged to smem once; 4 independent float4 gathers per thread (MLP 4).
// ---------------------------------------------------------------------------
__global__ __launch_bounds__(256) void gather_kernel(
    const float* __restrict__ emb, float* __restrict__ out)
{
    __shared__ int rows[64];
    const int m = blockIdx.y, t0 = blockIdx.x * 64;
    const int tid = threadIdx.x;
    if (tid < 64) rows[tid] = g_row[m * TOK + t0 + tid];
    __syncthreads();
    const float* E = emb + (size_t)m * (KR + 1) * DDIM;
    #pragma unroll
    for (int it = 0; it < 4; ++it) {
        int j = tid + it * 256;
        int t = j >> 4, dg = j & 15;
        int row = rows[t];
        float4 v;
        if (row) {
            v = *reinterpret_cast<const float4*>(E + (size_t)row * DDIM + dg * 4);
        } else {
            v = make_float4(0.f, 0.f, 0.f, 0.f);   // padding row is zero
        }
        *reinterpret_cast<float4*>(out + (size_t)(t0 + t) * CDIM + m * DDIM + dg * 4) = v;
    }
}

// ---------------------------------------------------------------------------
extern "C" void kernel_launch(void* const* d_in, const int* in_sizes, int n_in,
                              void* d_out, int out_size)
{
    (void)in_sizes; (void)n_in; (void)out_size;
    const float* x   = (const float*)d_in[0];
    const float* wq  = (const float*)d_in[1];
    const float* wk  = (const float*)d_in[2];
    const float* wv  = (const float*)d_in[3];
    const float* emb = (const float*)d_in[4];
    float* out = (float*)d_out;

    cudaFuncSetAttribute(tc_route_kernel,
                         cudaFuncAttributeMaxDynamicSharedMemorySize, SM_TOTAL);

    split_w_kernel<<<(3 * NHEAD * NTPM * 4 * 32) / 256, 256>>>(wq, wk, wv);
    tc_route_kernel<<<NCTA, 256, SM_TOTAL>>>(x);
    match_kernel<<<NHEAD, 1024>>>();
    dim3 g3(TOK / 64, NHEAD);
    gather_kernel<<<g3, 256>>>(emb, out);
}